// round 5
// baseline (speedup 1.0000x reference)
#include <cuda_runtime.h>

// Local contrast normalization, fused, pair-interleaved f32x2 + sliding windows.
// mean = conv9x9_gauss(x); d = x - mean; var = conv9x9_gauss(d*d);
// out = (var > 0.25) ? d * rsqrt(var) : d.  SAME zero-pad, separable kernel,
// taps u[i] = exp(-(i-4.5)^2/3)/S (asymmetric center).

typedef unsigned long long u64;
typedef ulonglong2 u64x2;

static constexpr int HH = 512, WW = 512;
static constexpr int TY = 32, TX = 64;

static constexpr int SXP = 164;  // sx: float, 24 row-pairs x 160 used (pair-interleaved)
static constexpr int STP = 50;   // stT: u64, 36 col-pairs x 48 y
static constexpr int SDP = 148;  // sd: float, 20 row-pairs x 144 used
static constexpr int T2P = 42;   // st2: u64, 32 col-pairs x 40 y (aliases stT)

#define K0 0.000381553f
#define K1 0.00549127f
#define K2 0.04057532f
#define K3 0.15392929f
#define K4 0.29981330f

union F2 { u64 v; float f[2]; };

__device__ __forceinline__ u64 pk(float a, float b) {
    F2 t; t.f[0] = a; t.f[1] = b; return t.v;
}
__device__ __forceinline__ u64 f2mul(u64 a, u64 b) {
    u64 d; asm("mul.rn.f32x2 %0, %1, %2;" : "=l"(d) : "l"(a), "l"(b)); return d;
}
__device__ __forceinline__ u64 f2fma(u64 a, u64 b, u64 c) {
    u64 d; asm("fma.rn.f32x2 %0, %1, %2, %3;" : "=l"(d) : "l"(a), "l"(b), "l"(c)); return d;
}

// 9-tap packed conv, single output, window a[0..8]
__device__ __forceinline__ u64 conv9(const u64* a, const u64 kv[5]) {
    u64 acc = f2mul(kv[0], a[0]);
    acc = f2fma(kv[1], a[1], acc);
    acc = f2fma(kv[2], a[2], acc);
    acc = f2fma(kv[3], a[3], acc);
    acc = f2fma(kv[4], a[4], acc);
    acc = f2fma(kv[4], a[5], acc);
    acc = f2fma(kv[3], a[6], acc);
    acc = f2fma(kv[2], a[7], acc);
    acc = f2fma(kv[1], a[8], acc);
    return acc;
}

__global__ __launch_bounds__(256)
void lcn_kernel(const float* __restrict__ x, float* __restrict__ out) {
    __shared__ __align__(16) float sxp[24 * SXP];   // x, row-pair interleaved
    __shared__ __align__(16) u64 sb[36 * STP];      // stT (col-pairs); reused as st2
    __shared__ __align__(16) float sdp[20 * SDP];   // d, row-pair interleaved

    const int tid = threadIdx.x;
    const int ox = blockIdx.x * TX;
    const int oy = blockIdx.y * TY;
    const long base = (long)blockIdx.z * (HH * WW);

    u64 kv[5];
    kv[0] = pk(K0, K0); kv[1] = pk(K1, K1); kv[2] = pk(K2, K2);
    kv[3] = pk(K3, K3); kv[4] = pk(K4, K4);
    const u64 neg1 = pk(-1.f, -1.f);
    const bool interior = (ox != 0) && (ox != WW - TX) && (oy != 0) && (oy != HH - TY);

    // ---------------- stage 0: load x tile, row-pair interleaved ----------------
    if (tid < 240) {
        int cg = tid % 10;
        int rp = tid / 10;
        int gye = oy - 8 + 2 * rp;
        int gx0 = ox - 8 + 8 * cg;
        const float* re = x + base + (long)gye * WW + gx0;
        float4 z = make_float4(0.f, 0.f, 0.f, 0.f);
        float4 e0 = z, e1 = z, o0 = z, o1 = z;
        bool rE = (unsigned)gye < (unsigned)HH;
        bool rO = (unsigned)(gye + 1) < (unsigned)HH;
        bool cA = (unsigned)gx0 < (unsigned)WW;
        bool cB = (unsigned)(gx0 + 4) < (unsigned)WW;
        if (rE && cA) e0 = *(const float4*)(re);
        if (rE && cB) e1 = *(const float4*)(re + 4);
        if (rO && cA) o0 = *(const float4*)(re + WW);
        if (rO && cB) o1 = *(const float4*)(re + WW + 4);
        float* d0 = sxp + rp * SXP + 16 * cg;
        ((float4*)d0)[0] = make_float4(e0.x, o0.x, e0.y, o0.y);
        ((float4*)d0)[1] = make_float4(e0.z, o0.z, e0.w, o0.w);
        ((float4*)d0)[2] = make_float4(e1.x, o1.x, e1.y, o1.y);
        ((float4*)d0)[3] = make_float4(e1.z, o1.z, e1.w, o1.w);
    }
    __syncthreads();

    // ------- stage 1: h-conv of x (y-pairs), 24 outputs/item -> stT (c-pairs) -------
    if (tid < 72) {
        int r = tid % 24;           // row pair (2r, 2r+1)
        int s = tid / 24;           // segment 0..2; out t-cols c0..c0+23
        const int c0 = 24 * s;
        const u64x2* p = (const u64x2*)(sxp + r * SXP + 2 * c0);
        u64 a[32];
        #pragma unroll
        for (int q = 0; q < 8; q++) { u64x2 v = p[q]; a[2*q] = v.x; a[2*q+1] = v.y; }
        #pragma unroll
        for (int m = 0; m < 4; m++) {
            F2 e, o; e.v = conv9(a + 2*m, kv); o.v = conv9(a + 2*m + 1, kv);
            u64x2 w; w.x = pk(e.f[0], o.f[0]); w.y = pk(e.f[1], o.f[1]);
            *(u64x2*)(sb + (12*s + m) * STP + 2*r) = w;
        }
        #pragma unroll
        for (int q = 8; q < 12; q++) { u64x2 v = p[q]; a[2*q] = v.x; a[2*q+1] = v.y; }
        #pragma unroll
        for (int m = 4; m < 8; m++) {
            F2 e, o; e.v = conv9(a + 2*m, kv); o.v = conv9(a + 2*m + 1, kv);
            u64x2 w; w.x = pk(e.f[0], o.f[0]); w.y = pk(e.f[1], o.f[1]);
            *(u64x2*)(sb + (12*s + m) * STP + 2*r) = w;
        }
        #pragma unroll
        for (int q = 12; q < 16; q++) { u64x2 v = p[q]; a[2*q] = v.x; a[2*q+1] = v.y; }
        #pragma unroll
        for (int m = 8; m < 12; m++) {
            F2 e, o; e.v = conv9(a + 2*m, kv); o.v = conv9(a + 2*m + 1, kv);
            u64x2 w; w.x = pk(e.f[0], o.f[0]); w.y = pk(e.f[1], o.f[1]);
            *(u64x2*)(sb + (12*s + m) * STP + 2*r) = w;
        }
    }
    __syncthreads();

    // ------- stage 2: v-conv -> mean; d = (x-mean)*mask, 20 rows/item -------
    if (tid < 72) {
        int cp = tid % 36;          // t col-pair (2cp, 2cp+1); gx = ox-4+2cp
        int h  = tid / 36;          // half: d rows y0..y0+19
        const int y0 = 20 * h;
        const u64x2* p = (const u64x2*)(sb + cp * STP + y0);
        u64 a[28];
        #pragma unroll
        for (int q = 0; q < 9; q++) { u64x2 v = p[q]; a[2*q] = v.x; a[2*q+1] = v.y; }

        int ce = ox - 4 + 2 * cp;
        float cE = ((unsigned)ce < (unsigned)WW) ? 1.f : 0.f;
        float cO = ((unsigned)(ce + 1) < (unsigned)WW) ? 1.f : 0.f;

        #pragma unroll
        for (int ph = 0; ph < 2; ph++) {
            if (ph == 1) {
                #pragma unroll
                for (int q = 9; q < 14; q++) { u64x2 v = p[q]; a[2*q] = v.x; a[2*q+1] = v.y; }
            }
            #pragma unroll
            for (int mm = 0; mm < 5; mm++) {
                int m = ph * 5 + mm;
                F2 p0, p1;
                p0.v = conv9(a + 2*m, kv);       // mean(y0+2m)   cols (2cp,2cp+1)
                p1.v = conv9(a + 2*m + 1, kv);   // mean(y0+2m+1)
                u64 meanE = pk(p0.f[0], p1.f[0]);
                u64 meanO = pk(p0.f[1], p1.f[1]);
                u64x2 xv = *(const u64x2*)(sxp + (10*h + m + 2) * SXP + 4*cp + 8);
                u64x2 w;
                if (interior) {
                    w.x = f2fma(meanE, neg1, xv.x);
                    w.y = f2fma(meanO, neg1, xv.y);
                } else {
                    int gy = oy - 4 + y0 + 2*m;
                    float r0 = ((unsigned)gy < (unsigned)HH) ? 1.f : 0.f;
                    float r1 = ((unsigned)(gy+1) < (unsigned)HH) ? 1.f : 0.f;
                    w.x = f2mul(f2fma(meanE, neg1, xv.x), pk(r0*cE, r1*cE));
                    w.y = f2mul(f2fma(meanO, neg1, xv.y), pk(r0*cO, r1*cO));
                }
                *(u64x2*)(sdp + (10*h + m) * SDP + 4*cp) = w;
            }
        }
    }
    __syncthreads();

    // ------- stage 3: h-conv of d^2 (y-pairs), 16 outputs/item -> st2 -------
    if (tid < 80) {
        int r = tid % 20;           // d row pair (2r, 2r+1)
        int s = tid / 20;           // segment 0..3; out cols c0..c0+15
        const int c0 = 16 * s;
        const u64x2* p = (const u64x2*)(sdp + r * SDP + 2 * c0);
        u64 a[24];
        #pragma unroll
        for (int q = 0; q < 8; q++) {
            u64x2 v = p[q];
            a[2*q]   = f2mul(v.x, v.x);
            a[2*q+1] = f2mul(v.y, v.y);
        }
        #pragma unroll
        for (int m = 0; m < 4; m++) {
            F2 e, o; e.v = conv9(a + 2*m, kv); o.v = conv9(a + 2*m + 1, kv);
            u64x2 w; w.x = pk(e.f[0], o.f[0]); w.y = pk(e.f[1], o.f[1]);
            *(u64x2*)(sb + (8*s + m) * T2P + 2*r) = w;
        }
        #pragma unroll
        for (int q = 8; q < 12; q++) {
            u64x2 v = p[q];
            a[2*q]   = f2mul(v.x, v.x);
            a[2*q+1] = f2mul(v.y, v.y);
        }
        #pragma unroll
        for (int m = 4; m < 8; m++) {
            F2 e, o; e.v = conv9(a + 2*m, kv); o.v = conv9(a + 2*m + 1, kv);
            u64x2 w; w.x = pk(e.f[0], o.f[0]); w.y = pk(e.f[1], o.f[1]);
            *(u64x2*)(sb + (8*s + m) * T2P + 2*r) = w;
        }
    }
    __syncthreads();

    // ------- stage 4: v-conv -> var; finalize; 16 rows/item -------
    if (tid < 64) {
        int cp = tid & 31;          // out col pair (ox+2cp, +1)
        int h  = tid >> 5;          // half: out rows y0..y0+15
        const int y0 = 16 * h;
        const u64x2* p = (const u64x2*)(sb + cp * T2P + y0);
        u64 a[24];
        #pragma unroll
        for (int q = 0; q < 8; q++) { u64x2 v = p[q]; a[2*q] = v.x; a[2*q+1] = v.y; }
        #pragma unroll
        for (int ph = 0; ph < 2; ph++) {
            if (ph == 1) {
                #pragma unroll
                for (int q = 8; q < 12; q++) { u64x2 v = p[q]; a[2*q] = v.x; a[2*q+1] = v.y; }
            }
            #pragma unroll
            for (int mm = 0; mm < 4; mm++) {
                int m = ph * 4 + mm;
                F2 V0, V1;
                V0.v = conv9(a + 2*m, kv);       // var(y0+2m)   cols (2cp,2cp+1)
                V1.v = conv9(a + 2*m + 1, kv);   // var(y0+2m+1)
                u64x2 dv = *(const u64x2*)(sdp + (8*h + m + 2) * SDP + 4*cp + 8);
                F2 A, B; A.v = dv.x; B.v = dv.y; // A: col even rows (r0,r1); B: col odd
                float m00 = (V0.f[0] > 0.25f) ? rsqrtf(V0.f[0]) : 1.f;
                float m01 = (V0.f[1] > 0.25f) ? rsqrtf(V0.f[1]) : 1.f;
                float m10 = (V1.f[0] > 0.25f) ? rsqrtf(V1.f[0]) : 1.f;
                float m11 = (V1.f[1] > 0.25f) ? rsqrtf(V1.f[1]) : 1.f;
                float2 r0 = make_float2(A.f[0] * m00, B.f[0] * m01);
                float2 r1 = make_float2(A.f[1] * m10, B.f[1] * m11);
                long o0 = base + (long)(oy + y0 + 2*m) * WW + (ox + 2*cp);
                *(float2*)(out + o0)      = r0;
                *(float2*)(out + o0 + WW) = r1;
            }
        }
    }
}

extern "C" void kernel_launch(void* const* d_in, const int* in_sizes, int n_in,
                              void* d_out, int out_size) {
    const float* x = (const float*)d_in[0];
    float* out = (float*)d_out;
    int B = in_sizes[0] / (HH * WW);
    dim3 grid(WW / TX, HH / TY, B);
    lcn_kernel<<<grid, 256>>>(x, out);
}